// round 8
// baseline (speedup 1.0000x reference)
#include <cuda_runtime.h>
#include <cstdint>

typedef unsigned long long ull;

#define BB    8192
#define LL    128
#define OO    512
#define KK    8
#define HH    20

#define OTILE   4      // o's per block, one per warp (128 threads)
#define BTILE   128    // b's per tile: lane, +32, +64, +96 per thread
#define NTILES  4      // b-tiles per block
#define XPAD    129    // x tile row pitch (floats): conflict-free gathers

// Per-o weight layout in DUPLICATED f32x2 pairs, stride 724 pairs:
//  [0,240)   : 20 blocks of 12 pairs: [W1[0..8][j], b1[j], pad, pad]
//  [240,720) : 20 blocks of 24 pairs: [W2[0..19][g], b2[g], W3[g], pad, pad]
//  [720]     : b3
#define WSTRIDE 724
#define WPAIRS  (OTILE * WSTRIDE)
#define XFLOATS (BTILE * XPAD)
#define SMEM_BYTES (WPAIRS * 8 + XFLOATS * 4)

static __device__ __forceinline__ ull pack2(float lo, float hi) {
    ull r; asm("mov.b64 %0, {%1, %2};" : "=l"(r) : "f"(lo), "f"(hi)); return r;
}
static __device__ __forceinline__ float2 unpack2(ull v) {
    float2 f; asm("mov.b64 {%0, %1}, %2;" : "=f"(f.x), "=f"(f.y) : "l"(v)); return f;
}
static __device__ __forceinline__ ull fma2(ull a, ull b, ull c) {
    ull d; asm("fma.rn.f32x2 %0, %1, %2, %3;" : "=l"(d) : "l"(a), "l"(b), "l"(c)); return d;
}
static __device__ __forceinline__ float tanh_f(float x) {
    float r; asm("tanh.approx.f32 %0, %1;" : "=f"(r) : "f"(x)); return r;
}
static __device__ __forceinline__ ull tanh2(ull v) {
    float2 f = unpack2(v);
    return pack2(tanh_f(f.x), tanh_f(f.y));
}

__global__ void __launch_bounds__(128, 2)
medil_kernel(const float* __restrict__ x,
             const float* __restrict__ noise,
             const int*   __restrict__ cause,
             const float* __restrict__ W1,
             const float* __restrict__ b1,
             const float* __restrict__ W2,
             const float* __restrict__ b2,
             const float* __restrict__ W3,
             const float* __restrict__ b3,
             float*       __restrict__ out)
{
    extern __shared__ __align__(16) char smem_raw[];
    ull*   wsm = (ull*)smem_raw;                       // 22.6 KB dup pairs (4 o)
    float* xsm = (float*)(smem_raw + WPAIRS * 8);      // 64.5 KB x tile (128 b)

    const int tid  = threadIdx.x;
    const int lane = tid & 31;
    const int warp = tid >> 5;
    const int oBase = blockIdx.x * OTILE;

    // ---- stage transposed, padded, duplicated weight pairs for 4 o's ----
#pragma unroll 1
    for (int idx = tid; idx < WPAIRS; idx += 128) {
        int ol  = idx / WSTRIDE;
        int off = idx - ol * WSTRIDE;
        int o   = oBase + ol;
        float v = 0.0f;
        if (off < 240) {
            int j = off / 12;
            int r = off - j * 12;
            if      (r < 9)  v = W1[o * 180 + r * 20 + j];
            else if (r == 9) v = b1[o * 20 + j];
        } else if (off < 720) {
            int t = off - 240;
            int g = t / 24;
            int r = t - g * 24;
            if      (r < 20)  v = W2[o * 400 + r * 20 + g];
            else if (r == 20) v = b2[o * 20 + g];
            else if (r == 21) v = W3[o * 20 + g];
        } else if (off == 720) {
            v = b3[o];
        }
        wsm[idx] = pack2(v, v);
    }

    const int o = oBase + warp;                 // this warp's output unit
    const ull* wb = wsm + warp * WSTRIDE;

    int c[KK];
    {
        int4 cA = *(const int4*)(cause + o * KK);
        int4 cB = *(const int4*)(cause + o * KK + 4);
        c[0] = cA.x; c[1] = cA.y; c[2] = cA.z; c[3] = cA.w;
        c[4] = cB.x; c[5] = cB.y; c[6] = cB.z; c[7] = cB.w;
    }

    const int bBlock = blockIdx.y * (NTILES * BTILE);

#pragma unroll 1
    for (int t = 0; t < NTILES; ++t) {
        const int b0 = bBlock + t * BTILE;

        __syncthreads();   // xsm reuse barrier (also orders wsm writes on t==0)

        // ---- stage x tile [128 b x 128 L] coalesced; pad rows to 129 ----
#pragma unroll 1
        for (int q = 0; q < 32; ++q) {
            int idx = q * 128 + tid;           // float4 index into 128x32 grid
            int row = idx >> 5;
            int c4  = idx & 31;
            float4 v = ((const float4*)(x + (size_t)(b0 + row) * LL))[c4];
            float* dst = xsm + row * XPAD + c4 * 4;
            dst[0] = v.x; dst[1] = v.y; dst[2] = v.z; dst[3] = v.w;
        }
        __syncthreads();

        const int bA = b0 + lane;              // 4 b's per thread
        const int bB = bA + 32;
        const int bC = bA + 64;
        const int bD = bA + 96;

        // ---- inputs: noise + gathers (conflict-free, pad 129) ----
        ull inpP[KK + 1], inpQ[KK + 1];
        inpP[0] = pack2(noise[(size_t)bA * OO + o], noise[(size_t)bB * OO + o]);
        inpQ[0] = pack2(noise[(size_t)bC * OO + o], noise[(size_t)bD * OO + o]);
        const float* xr0 = xsm + lane * XPAD;
        const float* xr1 = xr0 + 32 * XPAD;
        const float* xr2 = xr0 + 64 * XPAD;
        const float* xr3 = xr0 + 96 * XPAD;
#pragma unroll
        for (int k = 0; k < KK; k++) {
            inpP[k + 1] = pack2(xr0[c[k]], xr1[c[k]]);
            inpQ[k + 1] = pack2(xr2[c[k]], xr3[c[k]]);
        }

        // ---- layer 1: h[j] = tanh(b1[j] + sum_i inp[i]*W1[i][j]) ----
        ull hP[HH], hQ[HH];
#pragma unroll 1
        for (int j = 0; j < HH; j++) {
            const ulonglong2* wj = (const ulonglong2*)(wb + j * 12);
            ulonglong2 q0 = wj[0];
            ulonglong2 q1 = wj[1];
            ulonglong2 q2 = wj[2];
            ulonglong2 q3 = wj[3];
            ulonglong2 q4 = wj[4];   // W1[8][j], b1[j]
            ull aP = q4.y, aQ = q4.y;
            aP = fma2(inpP[0], q0.x, aP);  aQ = fma2(inpQ[0], q0.x, aQ);
            aP = fma2(inpP[1], q0.y, aP);  aQ = fma2(inpQ[1], q0.y, aQ);
            aP = fma2(inpP[2], q1.x, aP);  aQ = fma2(inpQ[2], q1.x, aQ);
            aP = fma2(inpP[3], q1.y, aP);  aQ = fma2(inpQ[3], q1.y, aQ);
            aP = fma2(inpP[4], q2.x, aP);  aQ = fma2(inpQ[4], q2.x, aQ);
            aP = fma2(inpP[5], q2.y, aP);  aQ = fma2(inpQ[5], q2.y, aQ);
            aP = fma2(inpP[6], q3.x, aP);  aQ = fma2(inpQ[6], q3.x, aQ);
            aP = fma2(inpP[7], q3.y, aP);  aQ = fma2(inpQ[7], q3.y, aQ);
            aP = fma2(inpP[8], q4.x, aP);  aQ = fma2(inpQ[8], q4.x, aQ);
            hP[j] = tanh2(aP);
            hQ[j] = tanh2(aQ);
        }

        // ---- layers 2+3 fused: acc += tanh(b2[g] + sum_j h[j]*W2[j][g]) * W3[g] ----
        ull accP = wb[720];                 // b3 pair
        ull accQ = accP;
#pragma unroll 1
        for (int g = 0; g < HH; g++) {
            const ulonglong2* wg = (const ulonglong2*)(wb + 240 + g * 24);
            ulonglong2 wt = wg[10];          // b2[g], W3[g]
            ull pP = wt.x, pQ = wt.x;
#pragma unroll
            for (int q = 0; q < 10; q++) {
                ulonglong2 w = wg[q];
                pP = fma2(hP[2 * q],     w.x, pP);
                pQ = fma2(hQ[2 * q],     w.x, pQ);
                pP = fma2(hP[2 * q + 1], w.y, pP);
                pQ = fma2(hQ[2 * q + 1], w.y, pQ);
            }
            accP = fma2(tanh2(pP), wt.y, accP);
            accQ = fma2(tanh2(pQ), wt.y, accQ);
        }

        float2 rP = unpack2(accP);
        float2 rQ = unpack2(accQ);
        out[(size_t)bA * OO + o] = rP.x;
        out[(size_t)bB * OO + o] = rP.y;
        out[(size_t)bC * OO + o] = rQ.x;
        out[(size_t)bD * OO + o] = rQ.y;
    }
}

extern "C" void kernel_launch(void* const* d_in, const int* in_sizes, int n_in,
                              void* d_out, int out_size)
{
    const float* x     = (const float*)d_in[0];
    const float* noise = (const float*)d_in[1];
    const int*   cause = (const int*)  d_in[2];
    const float* W1    = (const float*)d_in[3];
    const float* b1    = (const float*)d_in[4];
    const float* W2    = (const float*)d_in[5];
    const float* b2    = (const float*)d_in[6];
    const float* W3    = (const float*)d_in[7];
    const float* b3    = (const float*)d_in[8];
    float* out = (float*)d_out;

    cudaFuncSetAttribute(medil_kernel,
                         cudaFuncAttributeMaxDynamicSharedMemorySize, SMEM_BYTES);

    dim3 grid(OO / OTILE, BB / (NTILES * BTILE));   // (128, 16) = 2048 blocks
    medil_kernel<<<grid, 128, SMEM_BYTES>>>(x, noise, cause, W1, b1, W2, b2, W3, b3, out);
}

// round 9
// speedup vs baseline: 1.3678x; 1.3678x over previous
#include <cuda_runtime.h>
#include <cstdint>

typedef unsigned long long ull;

#define BB    8192
#define LL    128
#define OO    512
#define KK    8
#define HH    20

#define OTILE   8      // o's per block, one per warp (256 threads)
#define BTILE   64     // b's per tile: lane and lane+32 per thread
#define NTILES  8      // b-tiles per block
#define XPAD    129    // x tile row pitch (floats): conflict-free gathers

// Per-o weight layout (floats), NEURON-PAIRED, stride 644:
//  [0,200)   : 10 jp-blocks of 20: { (W1[i][2jp],W1[i][2jp+1]) i=0..8, (b1[2jp],b1[2jp+1]) }
//  [200,600) : 20 g-blocks of 20:  { (W2[2jp][g],W2[2jp+1][g]) jp=0..9 }
//  [600,640) : 20 float2: (b2[g], W3[g])
//  [640]     : b3   (+3 pad)
#define WSTRIDE 644
#define WFLOATS (OTILE * WSTRIDE)
#define XFLOATS (BTILE * XPAD)
#define SMEM_BYTES (WFLOATS * 4 + XFLOATS * 4)

static __device__ __forceinline__ ull pack2(float lo, float hi) {
    ull r; asm("mov.b64 %0, {%1, %2};" : "=l"(r) : "f"(lo), "f"(hi)); return r;
}
static __device__ __forceinline__ float2 unpack2(ull v) {
    float2 f; asm("mov.b64 {%0, %1}, %2;" : "=f"(f.x), "=f"(f.y) : "l"(v)); return f;
}
static __device__ __forceinline__ ull fma2(ull a, ull b, ull c) {
    ull d; asm("fma.rn.f32x2 %0, %1, %2, %3;" : "=l"(d) : "l"(a), "l"(b), "l"(c)); return d;
}
static __device__ __forceinline__ float tanh_f(float x) {
    float r; asm("tanh.approx.f32 %0, %1;" : "=f"(r) : "f"(x)); return r;
}
static __device__ __forceinline__ ull tanh2(ull v) {
    float2 f = unpack2(v);
    return pack2(tanh_f(f.x), tanh_f(f.y));
}

__global__ void __launch_bounds__(256, 2)
medil_kernel(const float* __restrict__ x,
             const float* __restrict__ noise,
             const int*   __restrict__ cause,
             const float* __restrict__ W1,
             const float* __restrict__ b1,
             const float* __restrict__ W2,
             const float* __restrict__ b2,
             const float* __restrict__ W3,
             const float* __restrict__ b3,
             float*       __restrict__ out)
{
    extern __shared__ __align__(16) char smem_raw[];
    float* wsm = (float*)smem_raw;                      // 20.6 KB weights (8 o)
    float* xsm = (float*)(smem_raw + WFLOATS * 4);      // 33 KB x tile (64 b)

    const int tid  = threadIdx.x;
    const int lane = tid & 31;
    const int warp = tid >> 5;
    const int oBase = blockIdx.x * OTILE;

    // ---- stage neuron-paired weights for 8 o's ----
#pragma unroll 1
    for (int idx = tid; idx < WFLOATS; idx += 256) {
        int ol  = idx / WSTRIDE;
        int off = idx - ol * WSTRIDE;
        int o   = oBase + ol;
        float v = 0.0f;
        if (off < 200) {
            int jp = off / 20;
            int r  = off - jp * 20;
            if (r < 18) { int i = r >> 1, sub = r & 1; v = W1[o * 180 + i * 20 + 2 * jp + sub]; }
            else        { v = b1[o * 20 + 2 * jp + (r - 18)]; }
        } else if (off < 600) {
            int t = off - 200;
            int g = t / 20;
            int r = t - g * 20;
            int jp = r >> 1, sub = r & 1;
            v = W2[o * 400 + (2 * jp + sub) * 20 + g];
        } else if (off < 640) {
            int t = off - 600;
            int g = t >> 1;
            v = (t & 1) ? W3[o * 20 + g] : b2[o * 20 + g];
        } else if (off == 640) {
            v = b3[o];
        }
        wsm[idx] = v;
    }

    const int o = oBase + warp;                 // this warp's output unit
    const float* wbF = wsm + warp * WSTRIDE;    // 16B-aligned (644*4 bytes % 16 == 0... 2576%16=0 ✓)

    int c[KK];
    {
        int4 cA = *(const int4*)(cause + o * KK);
        int4 cB = *(const int4*)(cause + o * KK + 4);
        c[0] = cA.x; c[1] = cA.y; c[2] = cA.z; c[3] = cA.w;
        c[4] = cB.x; c[5] = cB.y; c[6] = cB.z; c[7] = cB.w;
    }

    const int bBlock = blockIdx.y * (NTILES * BTILE);

#pragma unroll 1
    for (int t = 0; t < NTILES; ++t) {
        const int b0 = bBlock + t * BTILE;

        __syncthreads();   // xsm reuse barrier (also orders wsm writes on t==0)

        // ---- stage x tile [64 b x 128 L] coalesced, MLP=8; pad rows to 129 ----
        {
            int row  = tid >> 2;          // 0..63
            int col0 = (tid & 3) * 32;    // 0,32,64,96
            const float4* src = (const float4*)(x + (size_t)(b0 + row) * LL + col0);
            float* dst = xsm + row * XPAD + col0;
#pragma unroll
            for (int q = 0; q < 8; q++) {
                float4 v = src[q];
                dst[q * 4 + 0] = v.x;
                dst[q * 4 + 1] = v.y;
                dst[q * 4 + 2] = v.z;
                dst[q * 4 + 3] = v.w;
            }
        }
        __syncthreads();

        const int bA = b0 + lane;        // 2 b's per thread
        const int bB = bA + 32;

        // ---- inputs (dup pairs per b): inp*[0]=noise, [k+1]=x gather ----
        ull inp0[KK + 1], inp1[KK + 1];
        {
            float n0 = noise[(size_t)bA * OO + o];
            float n1 = noise[(size_t)bB * OO + o];
            inp0[0] = pack2(n0, n0);
            inp1[0] = pack2(n1, n1);
            const float* xr0 = xsm + lane * XPAD;
            const float* xr1 = xr0 + 32 * XPAD;
#pragma unroll
            for (int k = 0; k < KK; k++) {
                float v0 = xr0[c[k]];
                float v1 = xr1[c[k]];
                inp0[k + 1] = pack2(v0, v0);
                inp1[k + 1] = pack2(v1, v1);
            }
        }

        // ---- layer 1: hp[jp] = ( tanh(neuron 2jp), tanh(neuron 2jp+1) ) ----
        ull hp0[HH / 2], hp1[HH / 2];
#pragma unroll 1
        for (int jp = 0; jp < HH / 2; jp++) {
            const ulonglong2* wj = (const ulonglong2*)(wbF + jp * 20);
            ulonglong2 w01 = wj[0];   // pairs for i=0,1
            ulonglong2 w23 = wj[1];
            ulonglong2 w45 = wj[2];
            ulonglong2 w67 = wj[3];
            ulonglong2 w8b = wj[4];   // pair i=8, b1 pair
            ull a0 = w8b.y, a1 = w8b.y;
            a0 = fma2(inp0[0], w01.x, a0);  a1 = fma2(inp1[0], w01.x, a1);
            a0 = fma2(inp0[1], w01.y, a0);  a1 = fma2(inp1[1], w01.y, a1);
            a0 = fma2(inp0[2], w23.x, a0);  a1 = fma2(inp1[2], w23.x, a1);
            a0 = fma2(inp0[3], w23.y, a0);  a1 = fma2(inp1[3], w23.y, a1);
            a0 = fma2(inp0[4], w45.x, a0);  a1 = fma2(inp1[4], w45.x, a1);
            a0 = fma2(inp0[5], w45.y, a0);  a1 = fma2(inp1[5], w45.y, a1);
            a0 = fma2(inp0[6], w67.x, a0);  a1 = fma2(inp1[6], w67.x, a1);
            a0 = fma2(inp0[7], w67.y, a0);  a1 = fma2(inp1[7], w67.y, a1);
            a0 = fma2(inp0[8], w8b.x, a0);  a1 = fma2(inp1[8], w8b.x, a1);
            hp0[jp] = tanh2(a0);
            hp1[jp] = tanh2(a1);
        }

        // ---- layers 2+3: acc += tanh(b2[g] + hsum(sum_jp hp[jp]*w2pair)) * W3[g] ----
        float acc0 = wbF[640];
        float acc1 = acc0;
#pragma unroll 1
        for (int g = 0; g < HH; g++) {
            const ulonglong2* wg = (const ulonglong2*)(wbF + 200 + g * 20);
            ull p0 = 0ull, p1 = 0ull;
#pragma unroll
            for (int q = 0; q < 5; q++) {
                ulonglong2 w = wg[q];
                p0 = fma2(hp0[2 * q],     w.x, p0);
                p1 = fma2(hp1[2 * q],     w.x, p1);
                p0 = fma2(hp0[2 * q + 1], w.y, p0);
                p1 = fma2(hp1[2 * q + 1], w.y, p1);
            }
            float2 bw = *(const float2*)(wbF + 600 + 2 * g);   // (b2[g], W3[g])
            float2 s0 = unpack2(p0);
            float2 s1 = unpack2(p1);
            float t0 = tanh_f(s0.x + s0.y + bw.x);
            float t1 = tanh_f(s1.x + s1.y + bw.x);
            acc0 = fmaf(t0, bw.y, acc0);
            acc1 = fmaf(t1, bw.y, acc1);
        }

        out[(size_t)bA * OO + o] = acc0;
        out[(size_t)bB * OO + o] = acc1;
    }
}

extern "C" void kernel_launch(void* const* d_in, const int* in_sizes, int n_in,
                              void* d_out, int out_size)
{
    const float* x     = (const float*)d_in[0];
    const float* noise = (const float*)d_in[1];
    const int*   cause = (const int*)  d_in[2];
    const float* W1    = (const float*)d_in[3];
    const float* b1    = (const float*)d_in[4];
    const float* W2    = (const float*)d_in[5];
    const float* b2    = (const float*)d_in[6];
    const float* W3    = (const float*)d_in[7];
    const float* b3    = (const float*)d_in[8];
    float* out = (float*)d_out;

    cudaFuncSetAttribute(medil_kernel,
                         cudaFuncAttributeMaxDynamicSharedMemorySize, SMEM_BYTES);

    dim3 grid(OO / OTILE, BB / (NTILES * BTILE));   // (64, 16) = 1024 blocks
    medil_kernel<<<grid, 256, SMEM_BYTES>>>(x, noise, cause, W1, b1, W2, b2, W3, b3, out);
}

// round 10
// speedup vs baseline: 1.5885x; 1.1614x over previous
#include <cuda_runtime.h>
#include <cstdint>

typedef unsigned long long ull;

#define BB    8192
#define LL    128
#define OO    512
#define KK    8
#define HH    20

#define OTILE   8      // o's per block, one per warp (256 threads)
#define BTILE   128    // b's per tile: lane, +32, +64, +96 per thread
#define NTILES  4      // b-tiles per block
#define XPAD    129    // x tile row pitch (floats): conflict-free gathers

// Per-o weight layout (floats), NEURON-PAIRED, i-major layer 1, stride 644:
//  [0,180)   : 9 i-blocks of 20: { (W1[i][2jp],W1[i][2jp+1]) jp=0..9 }
//  [180,200) : 10 pairs (b1[2jp],b1[2jp+1])
//  [200,600) : 20 g-blocks of 20: { (W2[2jp][g],W2[2jp+1][g]) jp=0..9 }
//  [600,640) : 20 float2: (b2[g], W3[g])
//  [640]     : b3   (+3 pad)
#define WSTRIDE 644
#define WFLOATS (OTILE * WSTRIDE)
#define XFLOATS (BTILE * XPAD)
#define CS_INTS (OTILE * KK)
#define SMEM_BYTES (WFLOATS * 4 + XFLOATS * 4 + CS_INTS * 4)

static __device__ __forceinline__ ull pack2(float lo, float hi) {
    ull r; asm("mov.b64 %0, {%1, %2};" : "=l"(r) : "f"(lo), "f"(hi)); return r;
}
static __device__ __forceinline__ float2 unpack2(ull v) {
    float2 f; asm("mov.b64 {%0, %1}, %2;" : "=f"(f.x), "=f"(f.y) : "l"(v)); return f;
}
static __device__ __forceinline__ ull dup2(float v) {
    ull r; asm("mov.b64 %0, {%1, %1};" : "=l"(r) : "f"(v)); return r;
}
static __device__ __forceinline__ ull fma2(ull a, ull b, ull c) {
    ull d; asm("fma.rn.f32x2 %0, %1, %2, %3;" : "=l"(d) : "l"(a), "l"(b), "l"(c)); return d;
}
static __device__ __forceinline__ float tanh_f(float x) {
    float r; asm("tanh.approx.f32 %0, %1;" : "=f"(r) : "f"(x)); return r;
}
static __device__ __forceinline__ ull tanh2(ull v) {
    float2 f = unpack2(v);
    return pack2(tanh_f(f.x), tanh_f(f.y));
}

__global__ void __launch_bounds__(256, 2)
medil_kernel(const float* __restrict__ x,
             const float* __restrict__ noise,
             const int*   __restrict__ cause,
             const float* __restrict__ W1,
             const float* __restrict__ b1,
             const float* __restrict__ W2,
             const float* __restrict__ b2,
             const float* __restrict__ W3,
             const float* __restrict__ b3,
             float*       __restrict__ out)
{
    extern __shared__ __align__(16) char smem_raw[];
    float* wsm = (float*)smem_raw;                            // 20.6 KB weights
    float* xsm = (float*)(smem_raw + WFLOATS * 4);            // 66 KB x tile
    int*   csm = (int*)(smem_raw + WFLOATS * 4 + XFLOATS * 4); // 256 B cause idx

    const int tid  = threadIdx.x;
    const int lane = tid & 31;
    const int warp = tid >> 5;
    const int oBase = blockIdx.x * OTILE;

    // ---- stage neuron-paired weights (i-major L1) for 8 o's ----
#pragma unroll 1
    for (int idx = tid; idx < WFLOATS; idx += 256) {
        int ol  = idx / WSTRIDE;
        int off = idx - ol * WSTRIDE;
        int o   = oBase + ol;
        float v = 0.0f;
        if (off < 180) {
            int i = off / 20;
            int r = off - i * 20;          // pair-local: jp = r>>1, sub = r&1
            v = W1[o * 180 + i * 20 + r];  // W1 row i is already j-contiguous
        } else if (off < 200) {
            v = b1[o * 20 + (off - 180)];
        } else if (off < 600) {
            int t = off - 200;
            int g = t / 20;
            int r = t - g * 20;
            int jp = r >> 1, sub = r & 1;
            v = W2[o * 400 + (2 * jp + sub) * 20 + g];
        } else if (off < 640) {
            int t = off - 600;
            int g = t >> 1;
            v = (t & 1) ? W3[o * 20 + g] : b2[o * 20 + g];
        } else if (off == 640) {
            v = b3[o];
        }
        wsm[idx] = v;
    }
    // cause indices for the block's 8 o's (contiguous in gmem)
    if (tid < CS_INTS) csm[tid] = cause[oBase * KK + tid];

    const int o = oBase + warp;
    const float* wbF = wsm + warp * WSTRIDE;     // 2576 B stride, 16B aligned
    const int*   cw  = csm + warp * KK;

    const int bBlock = blockIdx.y * (NTILES * BTILE);

#pragma unroll 1
    for (int t = 0; t < NTILES; ++t) {
        const int b0 = bBlock + t * BTILE;

        __syncthreads();   // xsm reuse barrier (also orders wsm/csm on t==0)

        // ---- stage x tile [128 b x 128 L], MLP=8, two 64-row halves ----
        {
            int row  = tid >> 2;          // 0..63
            int col0 = (tid & 3) * 32;    // 0,32,64,96
#pragma unroll
            for (int hf = 0; hf < 2; ++hf) {
                const float4* src = (const float4*)(x + (size_t)(b0 + hf * 64 + row) * LL + col0);
                float* dst = xsm + (hf * 64 + row) * XPAD + col0;
#pragma unroll
                for (int q = 0; q < 8; q++) {
                    float4 v = src[q];
                    dst[q * 4 + 0] = v.x;
                    dst[q * 4 + 1] = v.y;
                    dst[q * 4 + 2] = v.z;
                    dst[q * 4 + 3] = v.w;
                }
            }
        }
        __syncthreads();

        const int bA = b0 + lane;         // 4 b's per thread
        const float* xr = xsm + lane * XPAD;

        // ---- layer 1, i-major: a[b][jp] accumulators (init fused with i=0) ----
        ull a0[HH / 2], a1[HH / 2], a2[HH / 2], a3[HH / 2];
        {
            ull d0 = dup2(noise[(size_t)(bA)      * OO + o]);
            ull d1 = dup2(noise[(size_t)(bA + 32) * OO + o]);
            ull d2 = dup2(noise[(size_t)(bA + 64) * OO + o]);
            ull d3 = dup2(noise[(size_t)(bA + 96) * OO + o]);
            const ulonglong2* w0 = (const ulonglong2*)(wbF);        // i=0 block
            const ulonglong2* wb = (const ulonglong2*)(wbF + 180);  // b1 pairs
#pragma unroll
            for (int q = 0; q < 5; q++) {
                ulonglong2 w = w0[q];
                ulonglong2 bq = wb[q];
                a0[2 * q]     = fma2(d0, w.x, bq.x);
                a1[2 * q]     = fma2(d1, w.x, bq.x);
                a2[2 * q]     = fma2(d2, w.x, bq.x);
                a3[2 * q]     = fma2(d3, w.x, bq.x);
                a0[2 * q + 1] = fma2(d0, w.y, bq.y);
                a1[2 * q + 1] = fma2(d1, w.y, bq.y);
                a2[2 * q + 1] = fma2(d2, w.y, bq.y);
                a3[2 * q + 1] = fma2(d3, w.y, bq.y);
            }
        }
#pragma unroll 1
        for (int i = 1; i <= KK; ++i) {
            int cc = cw[i - 1];           // uniform smem broadcast
            ull d0 = dup2(xr[cc]);
            ull d1 = dup2(xr[32 * XPAD + cc]);
            ull d2 = dup2(xr[64 * XPAD + cc]);
            ull d3 = dup2(xr[96 * XPAD + cc]);
            const ulonglong2* wi = (const ulonglong2*)(wbF + i * 20);
#pragma unroll
            for (int q = 0; q < 5; q++) {
                ulonglong2 w = wi[q];
                a0[2 * q]     = fma2(d0, w.x, a0[2 * q]);
                a1[2 * q]     = fma2(d1, w.x, a1[2 * q]);
                a2[2 * q]     = fma2(d2, w.x, a2[2 * q]);
                a3[2 * q]     = fma2(d3, w.x, a3[2 * q]);
                a0[2 * q + 1] = fma2(d0, w.y, a0[2 * q + 1]);
                a1[2 * q + 1] = fma2(d1, w.y, a1[2 * q + 1]);
                a2[2 * q + 1] = fma2(d2, w.y, a2[2 * q + 1]);
                a3[2 * q + 1] = fma2(d3, w.y, a3[2 * q + 1]);
            }
        }
#pragma unroll
        for (int jp = 0; jp < HH / 2; jp++) {
            a0[jp] = tanh2(a0[jp]);
            a1[jp] = tanh2(a1[jp]);
            a2[jp] = tanh2(a2[jp]);
            a3[jp] = tanh2(a3[jp]);
        }

        // ---- layers 2+3: acc += tanh(b2[g] + hsum(sum_jp hp*w2pair)) * W3[g] ----
        float acc0 = wbF[640], acc1 = acc0, acc2 = acc0, acc3 = acc0;
#pragma unroll 1
        for (int g = 0; g < HH; g++) {
            const ulonglong2* wg = (const ulonglong2*)(wbF + 200 + g * 20);
            ull p0 = 0ull, p1 = 0ull, p2 = 0ull, p3 = 0ull;
#pragma unroll
            for (int q = 0; q < 5; q++) {
                ulonglong2 w = wg[q];
                p0 = fma2(a0[2 * q],     w.x, p0);
                p1 = fma2(a1[2 * q],     w.x, p1);
                p2 = fma2(a2[2 * q],     w.x, p2);
                p3 = fma2(a3[2 * q],     w.x, p3);
                p0 = fma2(a0[2 * q + 1], w.y, p0);
                p1 = fma2(a1[2 * q + 1], w.y, p1);
                p2 = fma2(a2[2 * q + 1], w.y, p2);
                p3 = fma2(a3[2 * q + 1], w.y, p3);
            }
            float2 bw = *(const float2*)(wbF + 600 + 2 * g);   // (b2[g], W3[g])
            float2 s0 = unpack2(p0);
            float2 s1 = unpack2(p1);
            float2 s2 = unpack2(p2);
            float2 s3 = unpack2(p3);
            acc0 = fmaf(tanh_f(s0.x + s0.y + bw.x), bw.y, acc0);
            acc1 = fmaf(tanh_f(s1.x + s1.y + bw.x), bw.y, acc1);
            acc2 = fmaf(tanh_f(s2.x + s2.y + bw.x), bw.y, acc2);
            acc3 = fmaf(tanh_f(s3.x + s3.y + bw.x), bw.y, acc3);
        }

        out[(size_t)(bA)      * OO + o] = acc0;
        out[(size_t)(bA + 32) * OO + o] = acc1;
        out[(size_t)(bA + 64) * OO + o] = acc2;
        out[(size_t)(bA + 96) * OO + o] = acc3;
    }
}

extern "C" void kernel_launch(void* const* d_in, const int* in_sizes, int n_in,
                              void* d_out, int out_size)
{
    const float* x     = (const float*)d_in[0];
    const float* noise = (const float*)d_in[1];
    const int*   cause = (const int*)  d_in[2];
    const float* W1    = (const float*)d_in[3];
    const float* b1    = (const float*)d_in[4];
    const float* W2    = (const float*)d_in[5];
    const float* b2    = (const float*)d_in[6];
    const float* W3    = (const float*)d_in[7];
    const float* b3    = (const float*)d_in[8];
    float* out = (float*)d_out;

    cudaFuncSetAttribute(medil_kernel,
                         cudaFuncAttributeMaxDynamicSharedMemorySize, SMEM_BYTES);

    dim3 grid(OO / OTILE, BB / (NTILES * BTILE));   // (64, 16) = 1024 blocks
    medil_kernel<<<grid, 256, SMEM_BYTES>>>(x, noise, cause, W1, b1, W2, b2, W3, b3, out);
}

// round 11
// speedup vs baseline: 1.8295x; 1.1517x over previous
#include <cuda_runtime.h>
#include <cstdint>

typedef unsigned long long ull;

#define BB    8192
#define LL    128
#define OO    512
#define KK    8
#define HH    20

#define OTILE   4      // o's per block, one per warp (128 threads)
#define BPT     8      // b's per thread: lane + 32q
#define BTILE   256    // b's per block

// Per-o weight layout (floats), NEURON-PAIRED, i-major layer 1, stride 644:
//  [0,180)   : 9 i-blocks of 20: { (W1[i][2jp],W1[i][2jp+1]) jp=0..9 }
//  [180,200) : 10 pairs (b1[2jp],b1[2jp+1])
//  [200,600) : 20 g-blocks of 20: { (W2[2jp][g],W2[2jp+1][g]) jp=0..9 }
//  [600,640) : 20 float2: (b2[g], W3[g])
//  [640]     : b3   (+3 pad)
#define WSTRIDE 644
#define WFLOATS (OTILE * WSTRIDE)

// Transposed scratch (static device arrays; no runtime allocation)
__device__ float g_xT[LL * BB];        //  4 MB : xT[l][b]
__device__ float g_noiseT[OO * BB];    // 16 MB : noiseT[o][b]
__device__ float g_outT[OO * BB];      // 16 MB : outT[o][b]

static __device__ __forceinline__ ull pack2(float lo, float hi) {
    ull r; asm("mov.b64 %0, {%1, %2};" : "=l"(r) : "f"(lo), "f"(hi)); return r;
}
static __device__ __forceinline__ float2 unpack2(ull v) {
    float2 f; asm("mov.b64 {%0, %1}, %2;" : "=f"(f.x), "=f"(f.y) : "l"(v)); return f;
}
static __device__ __forceinline__ ull dup2(float v) {
    ull r; asm("mov.b64 %0, {%1, %1};" : "=l"(r) : "f"(v)); return r;
}
static __device__ __forceinline__ ull fma2(ull a, ull b, ull c) {
    ull d; asm("fma.rn.f32x2 %0, %1, %2, %3;" : "=l"(d) : "l"(a), "l"(b), "l"(c)); return d;
}
static __device__ __forceinline__ float tanh_f(float x) {
    float r; asm("tanh.approx.f32 %0, %1;" : "=f"(r) : "f"(x)); return r;
}
static __device__ __forceinline__ ull tanh2(ull v) {
    float2 f = unpack2(v);
    return pack2(tanh_f(f.x), tanh_f(f.y));
}

// ---------- tiled transpose: dst[c][r] = src[r][c] ----------
__global__ void __launch_bounds__(256)
transpose_k(const float* __restrict__ src, float* __restrict__ dst,
            int rows, int cols)
{
    __shared__ float tile[32][33];
    int c  = blockIdx.x * 32 + threadIdx.x;
    int r0 = blockIdx.y * 32;
#pragma unroll
    for (int j = 0; j < 32; j += 8)
        tile[threadIdx.y + j][threadIdx.x] =
            src[(size_t)(r0 + threadIdx.y + j) * cols + c];
    __syncthreads();
    int r  = r0 + threadIdx.x;
    int c0 = blockIdx.x * 32 + threadIdx.y;
#pragma unroll
    for (int j = 0; j < 32; j += 8)
        dst[(size_t)(c0 + j) * rows + r] = tile[threadIdx.x][threadIdx.y + j];
}

// ---------- main kernel ----------
__global__ void __launch_bounds__(128, 2)
medil_kernel(const int*   __restrict__ cause,
             const float* __restrict__ W1,
             const float* __restrict__ b1,
             const float* __restrict__ W2,
             const float* __restrict__ b2,
             const float* __restrict__ W3,
             const float* __restrict__ b3)
{
    __shared__ __align__(16) float wsm[WFLOATS];   // 10.3 KB
    __shared__ int csm[OTILE * KK];

    const int tid   = threadIdx.x;
    const int lane  = tid & 31;
    const int warp  = tid >> 5;
    const int oBase = blockIdx.x * OTILE;

    // ---- stage neuron-paired weights (i-major L1) for 4 o's ----
#pragma unroll 1
    for (int idx = tid; idx < WFLOATS; idx += 128) {
        int ol  = idx / WSTRIDE;
        int off = idx - ol * WSTRIDE;
        int o   = oBase + ol;
        float v = 0.0f;
        if (off < 180) {
            int i = off / 20;
            int r = off - i * 20;
            v = W1[o * 180 + i * 20 + r];
        } else if (off < 200) {
            v = b1[o * 20 + (off - 180)];
        } else if (off < 600) {
            int t = off - 200;
            int g = t / 20;
            int r = t - g * 20;
            int jp = r >> 1, sub = r & 1;
            v = W2[o * 400 + (2 * jp + sub) * 20 + g];
        } else if (off < 640) {
            int t = off - 600;
            int g = t >> 1;
            v = (t & 1) ? W3[o * 20 + g] : b2[o * 20 + g];
        } else if (off == 640) {
            v = b3[o];
        }
        wsm[idx] = v;
    }
    if (tid < OTILE * KK) csm[tid] = cause[oBase * KK + tid];
    __syncthreads();

    const int o = oBase + warp;
    const float* wbF = wsm + warp * WSTRIDE;
    const int*   cw  = csm + warp * KK;

    const int bb = blockIdx.y * BTILE + lane;   // 8 b's: bb + 32q

    // ---- gather pipeline: cur = noise (i=0 input), prefetch gather for i=1 ----
    float gc[BPT], gn[BPT];
    {
        const float* np = g_noiseT + (size_t)o * BB + bb;
#pragma unroll
        for (int q = 0; q < BPT; q++) gc[q] = np[32 * q];
        const float* xc = g_xT + (size_t)cw[0] * BB + bb;
#pragma unroll
        for (int q = 0; q < BPT; q++) gn[q] = xc[32 * q];
    }

    // ---- layer 1, i-major: a[q][jp], init fused with i=0 (noise) + b1 ----
    ull a[BPT][HH / 2];
    {
        const ulonglong2* w0 = (const ulonglong2*)(wbF);        // i=0 block
        const ulonglong2* wb = (const ulonglong2*)(wbF + 180);  // b1 pairs
        ull d[BPT];
#pragma unroll
        for (int q = 0; q < BPT; q++) d[q] = dup2(gc[q]);
#pragma unroll
        for (int qd = 0; qd < 5; qd++) {
            ulonglong2 w  = w0[qd];
            ulonglong2 bq = wb[qd];
#pragma unroll
            for (int q = 0; q < BPT; q++) {
                a[q][2 * qd]     = fma2(d[q], w.x, bq.x);
                a[q][2 * qd + 1] = fma2(d[q], w.y, bq.y);
            }
        }
    }
#pragma unroll 1
    for (int i = 1; i <= KK; ++i) {
#pragma unroll
        for (int q = 0; q < BPT; q++) gc[q] = gn[q];
        {
            int cn = cw[(i < KK) ? i : (KK - 1)];   // last prefetch harmless
            const float* xc = g_xT + (size_t)cn * BB + bb;
#pragma unroll
            for (int q = 0; q < BPT; q++) gn[q] = xc[32 * q];
        }
        const ulonglong2* wi = (const ulonglong2*)(wbF + i * 20);
        ull d[BPT];
#pragma unroll
        for (int q = 0; q < BPT; q++) d[q] = dup2(gc[q]);
#pragma unroll
        for (int qd = 0; qd < 5; qd++) {
            ulonglong2 w = wi[qd];
#pragma unroll
            for (int q = 0; q < BPT; q++) {
                a[q][2 * qd]     = fma2(d[q], w.x, a[q][2 * qd]);
                a[q][2 * qd + 1] = fma2(d[q], w.y, a[q][2 * qd + 1]);
            }
        }
    }
#pragma unroll
    for (int jp = 0; jp < HH / 2; jp++)
#pragma unroll
        for (int q = 0; q < BPT; q++)
            a[q][jp] = tanh2(a[q][jp]);

    // ---- layers 2+3: acc += tanh(b2[g] + hsum(sum_jp hp*w2pair)) * W3[g] ----
    float acc[BPT];
    {
        float b3v = wbF[640];
#pragma unroll
        for (int q = 0; q < BPT; q++) acc[q] = b3v;
    }
#pragma unroll 1
    for (int g = 0; g < HH; g++) {
        const ulonglong2* wg = (const ulonglong2*)(wbF + 200 + g * 20);
        ull p[BPT];
#pragma unroll
        for (int q = 0; q < BPT; q++) p[q] = 0ull;
#pragma unroll
        for (int qd = 0; qd < 5; qd++) {
            ulonglong2 w = wg[qd];
#pragma unroll
            for (int q = 0; q < BPT; q++) {
                p[q] = fma2(a[q][2 * qd],     w.x, p[q]);
                p[q] = fma2(a[q][2 * qd + 1], w.y, p[q]);
            }
        }
        float2 bw = *(const float2*)(wbF + 600 + 2 * g);   // (b2[g], W3[g])
#pragma unroll
        for (int q = 0; q < BPT; q++) {
            float2 s = unpack2(p[q]);
            acc[q] = fmaf(tanh_f(s.x + s.y + bw.x), bw.y, acc[q]);
        }
    }

    float* op = g_outT + (size_t)o * BB + bb;
#pragma unroll
    for (int q = 0; q < BPT; q++) op[32 * q] = acc[q];
}

extern "C" void kernel_launch(void* const* d_in, const int* in_sizes, int n_in,
                              void* d_out, int out_size)
{
    const float* x     = (const float*)d_in[0];
    const float* noise = (const float*)d_in[1];
    const int*   cause = (const int*)  d_in[2];
    const float* W1    = (const float*)d_in[3];
    const float* b1    = (const float*)d_in[4];
    const float* W2    = (const float*)d_in[5];
    const float* b2    = (const float*)d_in[6];
    const float* W3    = (const float*)d_in[7];
    const float* b3    = (const float*)d_in[8];
    float* out = (float*)d_out;

    float* xT;  float* nT;  float* oT;
    cudaGetSymbolAddress((void**)&xT, g_xT);
    cudaGetSymbolAddress((void**)&nT, g_noiseT);
    cudaGetSymbolAddress((void**)&oT, g_outT);

    dim3 tb(32, 8);
    // x [8192,128] -> xT [128,8192]
    transpose_k<<<dim3(LL / 32, BB / 32), tb>>>(x, xT, BB, LL);
    // noise [8192,512] -> noiseT [512,8192]
    transpose_k<<<dim3(OO / 32, BB / 32), tb>>>(noise, nT, BB, OO);

    dim3 grid(OO / OTILE, BB / BTILE);   // (128, 32) = 4096 blocks
    medil_kernel<<<grid, 128>>>(cause, W1, b1, W2, b2, W3, b3);

    // outT [512,8192] -> out [8192,512]
    transpose_k<<<dim3(BB / 32, OO / 32), tb>>>(oT, out, OO, BB);
}

// round 12
// speedup vs baseline: 2.1521x; 1.1763x over previous
#include <cuda_runtime.h>
#include <cstdint>

typedef unsigned long long ull;

#define BB    8192
#define LL    128
#define OO    512
#define KK    8
#define HH    20

#define OTILE   4      // o's per block, one per warp (128 threads)
#define BPT     8      // b's per thread in full blocks (grid covers BB exactly: 8192 = 32*256)
#define BTILE   256

// NOTE: to keep BB divisible by BTILE while raising occupancy, we keep BPT=8
// per thread but allow 3 CTAs/SM by capping regs at 170 and letting ptxas
// keep the hot accumulators resident; if it spills, DRAM% will show it.
// (BPT=6 would misalign the grid: 8192 % 192 != 0.)

#define WSTRIDE 644
#define WFLOATS (OTILE * WSTRIDE)

__device__ float g_xT[LL * BB];        //  4 MB : xT[l][b]
__device__ float g_noiseT[OO * BB];    // 16 MB : noiseT[o][b]
__device__ float g_outT[OO * BB];      // 16 MB : outT[o][b]

static __device__ __forceinline__ ull pack2(float lo, float hi) {
    ull r; asm("mov.b64 %0, {%1, %2};" : "=l"(r) : "f"(lo), "f"(hi)); return r;
}
static __device__ __forceinline__ float2 unpack2(ull v) {
    float2 f; asm("mov.b64 {%0, %1}, %2;" : "=f"(f.x), "=f"(f.y) : "l"(v)); return f;
}
static __device__ __forceinline__ ull dup2(float v) {
    ull r; asm("mov.b64 %0, {%1, %1};" : "=l"(r) : "f"(v)); return r;
}
static __device__ __forceinline__ ull fma2(ull a, ull b, ull c) {
    ull d; asm("fma.rn.f32x2 %0, %1, %2, %3;" : "=l"(d) : "l"(a), "l"(b), "l"(c)); return d;
}
static __device__ __forceinline__ float tanh_f(float x) {
    float r; asm("tanh.approx.f32 %0, %1;" : "=f"(r) : "f"(x)); return r;
}
static __device__ __forceinline__ ull tanh2(ull v) {
    float2 f = unpack2(v);
    return pack2(tanh_f(f.x), tanh_f(f.y));
}

__global__ void __launch_bounds__(256)
transpose_k(const float* __restrict__ src, float* __restrict__ dst,
            int rows, int cols)
{
    __shared__ float tile[32][33];
    int c  = blockIdx.x * 32 + threadIdx.x;
    int r0 = blockIdx.y * 32;
#pragma unroll
    for (int j = 0; j < 32; j += 8)
        tile[threadIdx.y + j][threadIdx.x] =
            src[(size_t)(r0 + threadIdx.y + j) * cols + c];
    __syncthreads();
    int r  = r0 + threadIdx.x;
    int c0 = blockIdx.x * 32 + threadIdx.y;
#pragma unroll
    for (int j = 0; j < 32; j += 8)
        dst[(size_t)(c0 + j) * rows + r] = tile[threadIdx.x][threadIdx.y + j];
}

// ---------- main kernel: 2 CTAs of 128 thr, split b-range into halves of 4 ----------
// Each thread handles 4 b's, twice (two passes) — same weight amortization as
// BPT=8 for LDS (weights stay in smem), but live regs ~ a[4][10]+pipeline ≈ 130
// -> fits 170-reg cap -> 3 CTAs/SM -> 12 warps.
#define BPP 4          // b's per pass
__global__ void __launch_bounds__(128, 3)
medil_kernel(const int*   __restrict__ cause,
             const float* __restrict__ W1,
             const float* __restrict__ b1,
             const float* __restrict__ W2,
             const float* __restrict__ b2,
             const float* __restrict__ W3,
             const float* __restrict__ b3)
{
    __shared__ __align__(16) float wsm[WFLOATS];
    __shared__ int csm[OTILE * KK];

    const int tid   = threadIdx.x;
    const int lane  = tid & 31;
    const int warp  = tid >> 5;
    const int oBase = blockIdx.x * OTILE;

#pragma unroll 1
    for (int idx = tid; idx < WFLOATS; idx += 128) {
        int ol  = idx / WSTRIDE;
        int off = idx - ol * WSTRIDE;
        int o   = oBase + ol;
        float v = 0.0f;
        if (off < 180) {
            int i = off / 20;
            int r = off - i * 20;
            v = W1[o * 180 + i * 20 + r];
        } else if (off < 200) {
            v = b1[o * 20 + (off - 180)];
        } else if (off < 600) {
            int t = off - 200;
            int g = t / 20;
            int r = t - g * 20;
            int jp = r >> 1, sub = r & 1;
            v = W2[o * 400 + (2 * jp + sub) * 20 + g];
        } else if (off < 640) {
            int t = off - 600;
            int g = t >> 1;
            v = (t & 1) ? W3[o * 20 + g] : b2[o * 20 + g];
        } else if (off == 640) {
            v = b3[o];
        }
        wsm[idx] = v;
    }
    if (tid < OTILE * KK) csm[tid] = cause[oBase * KK + tid];
    __syncthreads();

    const int o = oBase + warp;
    const float* wbF = wsm + warp * WSTRIDE;
    const int*   cw  = csm + warp * KK;

#pragma unroll 1
    for (int pass = 0; pass < 2; ++pass) {
        const int bb = blockIdx.y * BTILE + pass * (BTILE / 2) + lane;  // 4 b's: bb+32q

        float gc[BPP], gn[BPP];
        {
            const float* np = g_noiseT + (size_t)o * BB + bb;
#pragma unroll
            for (int q = 0; q < BPP; q++) gc[q] = np[32 * q];
            const float* xc = g_xT + (size_t)cw[0] * BB + bb;
#pragma unroll
            for (int q = 0; q < BPP; q++) gn[q] = xc[32 * q];
        }

        ull a[BPP][HH / 2];
        {
            const ulonglong2* w0 = (const ulonglong2*)(wbF);
            const ulonglong2* wb = (const ulonglong2*)(wbF + 180);
            ull d[BPP];
#pragma unroll
            for (int q = 0; q < BPP; q++) d[q] = dup2(gc[q]);
#pragma unroll
            for (int qd = 0; qd < 5; qd++) {
                ulonglong2 w  = w0[qd];
                ulonglong2 bq = wb[qd];
#pragma unroll
                for (int q = 0; q < BPP; q++) {
                    a[q][2 * qd]     = fma2(d[q], w.x, bq.x);
                    a[q][2 * qd + 1] = fma2(d[q], w.y, bq.y);
                }
            }
        }
#pragma unroll 1
        for (int i = 1; i <= KK; ++i) {
#pragma unroll
            for (int q = 0; q < BPP; q++) gc[q] = gn[q];
            {
                int cn = cw[(i < KK) ? i : (KK - 1)];
                const float* xc = g_xT + (size_t)cn * BB + bb;
#pragma unroll
                for (int q = 0; q < BPP; q++) gn[q] = xc[32 * q];
            }
            const ulonglong2* wi = (const ulonglong2*)(wbF + i * 20);
            ull d[BPP];
#pragma unroll
            for (int q = 0; q < BPP; q++) d[q] = dup2(gc[q]);
#pragma unroll
            for (int qd = 0; qd < 5; qd++) {
                ulonglong2 w = wi[qd];
#pragma unroll
                for (int q = 0; q < BPP; q++) {
                    a[q][2 * qd]     = fma2(d[q], w.x, a[q][2 * qd]);
                    a[q][2 * qd + 1] = fma2(d[q], w.y, a[q][2 * qd + 1]);
                }
            }
        }
#pragma unroll
        for (int jp = 0; jp < HH / 2; jp++)
#pragma unroll
            for (int q = 0; q < BPP; q++)
                a[q][jp] = tanh2(a[q][jp]);

        float acc[BPP];
        {
            float b3v = wbF[640];
#pragma unroll
            for (int q = 0; q < BPP; q++) acc[q] = b3v;
        }
#pragma unroll 1
        for (int g = 0; g < HH; g++) {
            const ulonglong2* wg = (const ulonglong2*)(wbF + 200 + g * 20);
            ull p[BPP];
#pragma unroll
            for (int q = 0; q < BPP; q++) p[q] = 0ull;
#pragma unroll
            for (int qd = 0; qd < 5; qd++) {
                ulonglong2 w = wg[qd];
#pragma unroll
                for (int q = 0; q < BPP; q++) {
                    p[q] = fma2(a[q][2 * qd],     w.x, p[q]);
                    p[q] = fma2(a[q][2 * qd + 1], w.y, p[q]);
                }
            }
            float2 bw = *(const float2*)(wbF + 600 + 2 * g);
#pragma unroll
            for (int q = 0; q < BPP; q++) {
                float2 s = unpack2(p[q]);
                acc[q] = fmaf(tanh_f(s.x + s.y + bw.x), bw.y, acc[q]);
            }
        }

        float* op = g_outT + (size_t)o * BB + bb;
#pragma unroll
        for (int q = 0; q < BPP; q++) op[32 * q] = acc[q];
    }
}

extern "C" void kernel_launch(void* const* d_in, const int* in_sizes, int n_in,
                              void* d_out, int out_size)
{
    const float* x     = (const float*)d_in[0];
    const float* noise = (const float*)d_in[1];
    const int*   cause = (const int*)  d_in[2];
    const float* W1    = (const float*)d_in[3];
    const float* b1    = (const float*)d_in[4];
    const float* W2    = (const float*)d_in[5];
    const float* b2    = (const float*)d_in[6];
    const float* W3    = (const float*)d_in[7];
    const float* b3    = (const float*)d_in[8];
    float* out = (float*)d_out;

    float* xT;  float* nT;  float* oT;
    cudaGetSymbolAddress((void**)&xT, g_xT);
    cudaGetSymbolAddress((void**)&nT, g_noiseT);
    cudaGetSymbolAddress((void**)&oT, g_outT);

    dim3 tb(32, 8);
    transpose_k<<<dim3(LL / 32, BB / 32), tb>>>(x, xT, BB, LL);
    transpose_k<<<dim3(OO / 32, BB / 32), tb>>>(noise, nT, BB, OO);

    medil_kernel<<<dim3(OO / OTILE, BB / BTILE), 128>>>(cause, W1, b1, W2, b2, W3, b3);

    transpose_k<<<dim3(BB / 32, OO / 32), tb>>>(oT, out, OO, BB);
}

// round 13
// speedup vs baseline: 2.1832x; 1.0144x over previous
#include <cuda_runtime.h>
#include <cstdint>

typedef unsigned long long ull;

#define BB    8192
#define LL    128
#define OO    512
#define KK    8
#define HH    20

#define OTILE   4      // o's per block, one per warp (128 threads)
#define BTILE   256    // b's per block (2 passes x 4 per thread x 32 lanes)
#define BPP     4      // b's per pass per thread

#define WSTRIDE 644
#define WFLOATS (OTILE * WSTRIDE)

__device__ float g_xT[LL * BB];        //  4 MB : xT[l][b]
__device__ float g_noiseT[OO * BB];    // 16 MB : noiseT[o][b]
__device__ float g_outT[OO * BB];      // 16 MB : outT[o][b]

static __device__ __forceinline__ ull pack2(float lo, float hi) {
    ull r; asm("mov.b64 %0, {%1, %2};" : "=l"(r) : "f"(lo), "f"(hi)); return r;
}
static __device__ __forceinline__ float2 unpack2(ull v) {
    float2 f; asm("mov.b64 {%0, %1}, %2;" : "=f"(f.x), "=f"(f.y) : "l"(v)); return f;
}
static __device__ __forceinline__ ull dup2(float v) {
    ull r; asm("mov.b64 %0, {%1, %1};" : "=l"(r) : "f"(v)); return r;
}
static __device__ __forceinline__ ull fma2(ull a, ull b, ull c) {
    ull d; asm("fma.rn.f32x2 %0, %1, %2, %3;" : "=l"(d) : "l"(a), "l"(b), "l"(c)); return d;
}
static __device__ __forceinline__ float tanh_f(float x) {
    float r; asm("tanh.approx.f32 %0, %1;" : "=f"(r) : "f"(x)); return r;
}
static __device__ __forceinline__ ull tanh2(ull v) {
    float2 f = unpack2(v);
    return pack2(tanh_f(f.x), tanh_f(f.y));
}

__global__ void __launch_bounds__(256)
transpose_k(const float* __restrict__ src, float* __restrict__ dst,
            int rows, int cols)
{
    __shared__ float tile[32][33];
    int c  = blockIdx.x * 32 + threadIdx.x;
    int r0 = blockIdx.y * 32;
#pragma unroll
    for (int j = 0; j < 32; j += 8)
        tile[threadIdx.y + j][threadIdx.x] =
            src[(size_t)(r0 + threadIdx.y + j) * cols + c];
    __syncthreads();
    int r  = r0 + threadIdx.x;
    int c0 = blockIdx.x * 32 + threadIdx.y;
#pragma unroll
    for (int j = 0; j < 32; j += 8)
        dst[(size_t)(c0 + j) * rows + r] = tile[threadIdx.x][threadIdx.y + j];
}

__global__ void __launch_bounds__(128, 4)
medil_kernel(const int*   __restrict__ cause,
             const float* __restrict__ W1,
             const float* __restrict__ b1,
             const float* __restrict__ W2,
             const float* __restrict__ b2,
             const float* __restrict__ W3,
             const float* __restrict__ b3)
{
    __shared__ __align__(16) float wsm[WFLOATS];
    __shared__ int csm[OTILE * KK];

    const int tid   = threadIdx.x;
    const int lane  = tid & 31;
    const int warp  = tid >> 5;
    const int oBase = blockIdx.x * OTILE;

#pragma unroll 1
    for (int idx = tid; idx < WFLOATS; idx += 128) {
        int ol  = idx / WSTRIDE;
        int off = idx - ol * WSTRIDE;
        int o   = oBase + ol;
        float v = 0.0f;
        if (off < 180) {
            int i = off / 20;
            int r = off - i * 20;
            v = W1[o * 180 + i * 20 + r];
        } else if (off < 200) {
            v = b1[o * 20 + (off - 180)];
        } else if (off < 600) {
            int t = off - 200;
            int g = t / 20;
            int r = t - g * 20;
            int jp = r >> 1, sub = r & 1;
            v = W2[o * 400 + (2 * jp + sub) * 20 + g];
        } else if (off < 640) {
            int t = off - 600;
            int g = t >> 1;
            v = (t & 1) ? W3[o * 20 + g] : b2[o * 20 + g];
        } else if (off == 640) {
            v = b3[o];
        }
        wsm[idx] = v;
    }
    if (tid < OTILE * KK) csm[tid] = cause[oBase * KK + tid];
    __syncthreads();

    const int o = oBase + warp;
    const float* wbF = wsm + warp * WSTRIDE;
    const int*   cw  = csm + warp * KK;

#pragma unroll 1
    for (int pass = 0; pass < 2; ++pass) {
        const int bb = blockIdx.y * BTILE + pass * (BTILE / 2) + lane;  // 4 b's: bb+32q

        // ---- gather pipeline: gn = prefetch buffer, d = dup'd current ----
        float gn[BPP];
        ull   d[BPP];
        {
            const float* np = g_noiseT + (size_t)o * BB + bb;
#pragma unroll
            for (int q = 0; q < BPP; q++) gn[q] = np[32 * q];
        }

        ull a[BPP][HH / 2];
        {
            // i = 0 (noise): convert, then prefetch cw[0]
#pragma unroll
            for (int q = 0; q < BPP; q++) d[q] = dup2(gn[q]);
            const float* xc = g_xT + (size_t)cw[0] * BB + bb;
#pragma unroll
            for (int q = 0; q < BPP; q++) gn[q] = xc[32 * q];

            const ulonglong2* w0 = (const ulonglong2*)(wbF);        // i=0 block
            const ulonglong2* wb = (const ulonglong2*)(wbF + 180);  // b1 pairs
#pragma unroll
            for (int qd = 0; qd < 5; qd++) {
                ulonglong2 w  = w0[qd];
                ulonglong2 bq = wb[qd];
#pragma unroll
                for (int q = 0; q < BPP; q++) {
                    a[q][2 * qd]     = fma2(d[q], w.x, bq.x);
                    a[q][2 * qd + 1] = fma2(d[q], w.y, bq.y);
                }
            }
        }
#pragma unroll 1
        for (int i = 1; i <= KK; ++i) {
#pragma unroll
            for (int q = 0; q < BPP; q++) d[q] = dup2(gn[q]);
            {
                int cn = cw[(i < KK) ? i : (KK - 1)];   // last prefetch harmless
                const float* xc = g_xT + (size_t)cn * BB + bb;
#pragma unroll
                for (int q = 0; q < BPP; q++) gn[q] = xc[32 * q];
            }
            const ulonglong2* wi = (const ulonglong2*)(wbF + i * 20);
#pragma unroll
            for (int qd = 0; qd < 5; qd++) {
                ulonglong2 w = wi[qd];
#pragma unroll
                for (int q = 0; q < BPP; q++) {
                    a[q][2 * qd]     = fma2(d[q], w.x, a[q][2 * qd]);
                    a[q][2 * qd + 1] = fma2(d[q], w.y, a[q][2 * qd + 1]);
                }
            }
        }
#pragma unroll
        for (int jp = 0; jp < HH / 2; jp++)
#pragma unroll
            for (int q = 0; q < BPP; q++)
                a[q][jp] = tanh2(a[q][jp]);

        float acc[BPP];
        {
            float b3v = wbF[640];
#pragma unroll
            for (int q = 0; q < BPP; q++) acc[q] = b3v;
        }
#pragma unroll 1
        for (int g = 0; g < HH; g++) {
            const ulonglong2* wg = (const ulonglong2*)(wbF + 200 + g * 20);
            ull p[BPP];
#pragma unroll
            for (int q = 0; q < BPP; q++) p[q] = 0ull;
#pragma unroll
            for (int qd = 0; qd < 5; qd++) {
                ulonglong2 w = wg[qd];
#pragma unroll
                for (int q = 0; q < BPP; q++) {
                    p[q] = fma2(a[q][2 * qd],     w.x, p[q]);
                    p[q] = fma2(a[q][2 * qd + 1], w.y, p[q]);
                }
            }
            float2 bw = *(const float2*)(wbF + 600 + 2 * g);   // (b2[g], W3[g])
#pragma unroll
            for (int q = 0; q < BPP; q++) {
                float2 s = unpack2(p[q]);
                acc[q] = fmaf(tanh_f(s.x + s.y + bw.x), bw.y, acc[q]);
            }
        }

        float* op = g_outT + (size_t)o * BB + bb;
#pragma unroll
        for (int q = 0; q < BPP; q++) op[32 * q] = acc[q];
    }
}

extern "C" void kernel_launch(void* const* d_in, const int* in_sizes, int n_in,
                              void* d_out, int out_size)
{
    const float* x     = (const float*)d_in[0];
    const float* noise = (const float*)d_in[1];
    const int*   cause = (const int*)  d_in[2];
    const float* W1    = (const float*)d_in[3];
    const float* b1    = (const float*)d_in[4];
    const float* W2    = (const float*)d_in[5];
    const float* b2    = (const float*)d_in[6];
    const float* W3    = (const float*)d_in[7];
    const float* b3    = (const float*)d_in[8];
    float* out = (float*)d_out;

    float* xT;  float* nT;  float* oT;
    cudaGetSymbolAddress((void**)&xT, g_xT);
    cudaGetSymbolAddress((void**)&nT, g_noiseT);
    cudaGetSymbolAddress((void**)&oT, g_outT);

    dim3 tb(32, 8);
    transpose_k<<<dim3(LL / 32, BB / 32), tb>>>(x, xT, BB, LL);
    transpose_k<<<dim3(OO / 32, BB / 32), tb>>>(noise, nT, BB, OO);

    medil_kernel<<<dim3(OO / OTILE, BB / BTILE), 128>>>(cause, W1, b1, W2, b2, W3, b3);

    transpose_k<<<dim3(BB / 32, OO / 32), tb>>>(oT, out, OO, BB);
}